// round 12
// baseline (speedup 1.0000x reference)
#include <cuda_runtime.h>
#include <cuda_fp16.h>
#include <stdint.h>

#define S_LEN   4096
#define DMODEL  1024
#define NHEADS  8
#define HDIM    128
#define NHID    2048
#define EPSN    1e-6f
#define CHUNK   64
#define NCHUNK  (NHID / CHUNK)

// ---------------------------------------------------------------------------
// Scratch (device globals — no allocations allowed)
// ---------------------------------------------------------------------------
__device__ __align__(16) __half g_qh[(size_t)S_LEN * DMODEL];
__device__ __align__(16) __half g_kh[(size_t)NHID * NHEADS * HDIM];
__device__ __align__(16) __half g_vth[(size_t)NHEADS * HDIM * NHID];
__device__ __align__(16) __half g_yh[(size_t)S_LEN * DMODEL];

// ---------------------------------------------------------------------------
// PTX helpers (baseline sm_80+ only)
// ---------------------------------------------------------------------------
__device__ __forceinline__ uint32_t smem_u32(const void* p) {
    uint32_t a;
    asm("{ .reg .u64 t; cvta.to.shared.u64 t, %1; cvt.u32.u64 %0, t; }"
        : "=r"(a) : "l"(p));
    return a;
}
__device__ __forceinline__ void cp16(uint32_t s, const void* g) {
    asm volatile("cp.async.cg.shared.global [%0], [%1], 16;" :: "r"(s), "l"(g));
}
#define CP_COMMIT() asm volatile("cp.async.commit_group;" ::: "memory")
#define CP_WAIT(n)  asm volatile("cp.async.wait_group %0;" :: "n"(n) : "memory")

__device__ __forceinline__ void ldsm4(uint32_t& r0, uint32_t& r1,
                                      uint32_t& r2, uint32_t& r3, uint32_t a) {
    asm volatile("ldmatrix.sync.aligned.m8n8.x4.shared.b16 {%0,%1,%2,%3}, [%4];"
                 : "=r"(r0), "=r"(r1), "=r"(r2), "=r"(r3) : "r"(a));
}
__device__ __forceinline__ void ldsm4t(uint32_t& r0, uint32_t& r1,
                                       uint32_t& r2, uint32_t& r3, uint32_t a) {
    asm volatile("ldmatrix.sync.aligned.m8n8.x4.trans.shared.b16 {%0,%1,%2,%3}, [%4];"
                 : "=r"(r0), "=r"(r1), "=r"(r2), "=r"(r3) : "r"(a));
}
__device__ __forceinline__ void mma_f16(float* d, const uint32_t* a, const uint32_t* b) {
    asm volatile(
        "mma.sync.aligned.m16n8k16.row.col.f32.f16.f16.f32 "
        "{%0,%1,%2,%3}, {%4,%5,%6,%7}, {%8,%9}, {%0,%1,%2,%3};"
        : "+f"(d[0]), "+f"(d[1]), "+f"(d[2]), "+f"(d[3])
        : "r"(a[0]), "r"(a[1]), "r"(a[2]), "r"(a[3]), "r"(b[0]), "r"(b[1]));
}
__device__ __forceinline__ uint32_t pkh(float x, float y) {
    __half2 h = __floats2half2_rn(x, y);
    return *reinterpret_cast<uint32_t*>(&h);
}
// SW64 swizzle (64B rows): XOR bits[4:5] with row bits[1:2]
__device__ __forceinline__ uint32_t sw64(uint32_t off) {
    return off ^ ((off >> 3) & 0x30u);
}

// ---------------------------------------------------------------------------
// Fused attention (fp16, all 1-term), SW64 layout, 2 CTAs/SM (round-9/10 proven).
// ---------------------------------------------------------------------------
#define SQ   0u
#define SK0  32768u
#define SK1  49152u
#define SV0  65536u
#define SV1  81920u
#define SMEM_ATTN 98304

__global__ __launch_bounds__(256, 2)
void attn_fused(const __half* __restrict__ qh,
                const __half* __restrict__ kh,
                const __half* __restrict__ vth,
                __half* __restrict__ yh)
{
    extern __shared__ char smem[];
    const uint32_t sb = smem_u32(smem);
    const int tid = threadIdx.x;
    const int w = tid >> 5, lane = tid & 31;
    const int h = blockIdx.y;
    const int qrow0 = blockIdx.x * 128;

    const __half* qhp = qh + (size_t)qrow0 * DMODEL + h * HDIM;
    const __half* khp = kh + h * HDIM;
    const __half* vhp = vth + (size_t)h * HDIM * NHID;

    #pragma unroll
    for (int it = 0; it < 8; it++) {
        int i = tid + it * 256;
        int s = i >> 9, r = (i >> 2) & 127, c16 = i & 3;
        uint32_t sa = sb + SQ + (uint32_t)(s * 8192) + sw64((uint32_t)(r * 64 + c16 * 16));
        cp16(sa, qhp + (size_t)r * DMODEL + s * 32 + c16 * 8);
    }
    CP_COMMIT();

    auto loadK = [&](int c) {
        const uint32_t kb = sb + ((c & 1) ? SK1 : SK0);
        const int j0 = c * CHUNK;
        #pragma unroll
        for (int it = 0; it < 4; it++) {
            int i = tid + it * 256;
            int s = i >> 8, r = (i >> 2) & 63, c16 = i & 3;
            uint32_t sa = kb + (uint32_t)(s * 4096) + sw64((uint32_t)(r * 64 + c16 * 16));
            cp16(sa, khp + (size_t)(j0 + r) * DMODEL + s * 32 + c16 * 8);
        }
    };
    auto loadV = [&](int c) {
        const uint32_t vb = sb + ((c & 1) ? SV1 : SV0);
        const int j0 = c * CHUNK;
        #pragma unroll
        for (int it = 0; it < 4; it++) {
            int i = tid + it * 256;
            int s = i >> 9, r = (i >> 2) & 127, c16 = i & 3;
            uint32_t sa = vb + (uint32_t)(s * 8192) + sw64((uint32_t)(r * 64 + c16 * 16));
            cp16(sa, vhp + (size_t)r * NHID + j0 + s * 32 + c16 * 8);
        }
    };

    loadK(0); loadV(0); CP_COMMIT();
    loadK(1); loadV(1); CP_COMMIT();

    const int row_a = w * 16 + (lane & 15);
    const uint32_t qrowpart = (uint32_t)(row_a * 64 + (lane >> 4) * 16);
    const uint32_t qxor = (uint32_t)((row_a & 6) << 3);
    const int row_b = ((lane >> 4) << 3) + (lane & 7);
    const uint32_t browpart = (uint32_t)(row_b * 64 + ((lane >> 3) & 1) * 16);
    const uint32_t bxor = (uint32_t)((row_b & 6) << 3);

    float Y[16][4];
    #pragma unroll
    for (int i = 0; i < 16; i++)
        #pragma unroll
        for (int j = 0; j < 4; j++) Y[i][j] = 0.0f;
    float l0 = 0.0f, l1 = 0.0f;

    for (int c = 0; c < NCHUNK; c++) {
        CP_WAIT(1);
        __syncthreads();

        const uint32_t kb = sb + ((c & 1) ? SK1 : SK0);
        float S[8][4];
        #pragma unroll
        for (int i = 0; i < 8; i++)
            #pragma unroll
            for (int j = 0; j < 4; j++) S[i][j] = 0.0f;

        #pragma unroll
        for (int kk = 0; kk < 8; kk++) {
            uint32_t kko = (uint32_t)((kk & 1) * 32);
            uint32_t qaddr = sb + SQ + (uint32_t)((kk >> 1) * 8192)
                           + ((qrowpart | kko) ^ qxor);
            uint32_t ah[4];
            ldsm4(ah[0], ah[1], ah[2], ah[3], qaddr);
            uint32_t bh[8][2];
            #pragma unroll
            for (int p = 0; p < 4; p++) {
                uint32_t ka = kb + (uint32_t)((kk >> 1) * 4096 + p * 1024)
                            + ((browpart | kko) ^ bxor);
                ldsm4(bh[2*p][0], bh[2*p][1], bh[2*p+1][0], bh[2*p+1][1], ka);
            }
            #pragma unroll
            for (int nt = 0; nt < 8; nt++)
                mma_f16(S[nt], ah, bh[nt]);
        }

        uint32_t pa[4][4];
        #pragma unroll
        for (int kk2 = 0; kk2 < 4; kk2++) {
            #pragma unroll
            for (int half = 0; half < 2; half++) {
                int nt = 2 * kk2 + half;
                float e0 = __expf(S[nt][0]);
                float e1 = __expf(S[nt][1]);
                float e2 = __expf(S[nt][2]);
                float e3 = __expf(S[nt][3]);
                l0 += e0 + e1;
                l1 += e2 + e3;
                pa[kk2][2*half]     = pkh(e0, e1);
                pa[kk2][2*half + 1] = pkh(e2, e3);
            }
        }

        const uint32_t vb = sb + ((c & 1) ? SV1 : SV0);
        #pragma unroll
        for (int kk2 = 0; kk2 < 4; kk2++) {
            uint32_t kko = (uint32_t)((kk2 & 1) * 32);
            #pragma unroll
            for (int p = 0; p < 8; p++) {
                uint32_t va = vb + (uint32_t)((kk2 >> 1) * 8192 + p * 1024)
                            + ((browpart | kko) ^ bxor);
                uint32_t vh[4];
                ldsm4(vh[0], vh[1], vh[2], vh[3], va);
                uint32_t b0[2] = {vh[0], vh[1]}, b1[2] = {vh[2], vh[3]};
                mma_f16(Y[2*p],     pa[kk2], b0);
                mma_f16(Y[2*p + 1], pa[kk2], b1);
            }
        }
        __syncthreads();

        if (c + 2 < NCHUNK) { loadK(c + 2); loadV(c + 2); }
        CP_COMMIT();
    }

    #pragma unroll
    for (int o = 1; o <= 2; o <<= 1) {
        l0 += __shfl_xor_sync(0xFFFFFFFFu, l0, o);
        l1 += __shfl_xor_sync(0xFFFFFFFFu, l1, o);
    }
    const float r0 = 1.0f / l0, r1 = 1.0f / l1;
    const int g = lane >> 2, colb = (lane & 3) * 2;
    #pragma unroll
    for (int nt = 0; nt < 16; nt++) {
        uint32_t h01 = pkh(Y[nt][0] * r0, Y[nt][1] * r0);
        uint32_t h23 = pkh(Y[nt][2] * r1, Y[nt][3] * r1);
        size_t o0 = (size_t)(qrow0 + w * 16 + g) * DMODEL + h * HDIM + nt * 8 + colb;
        *reinterpret_cast<uint32_t*>(yh + o0) = h01;
        *reinterpret_cast<uint32_t*>(yh + o0 + (size_t)8 * DMODEL) = h23;
    }
}

// ---------------------------------------------------------------------------
// 1-term fp16 HMMA GEMM, 3-stage, single barrier/iter.
// B is ALWAYS fp32 in gmem, K-major rows [k][n] (raw Wq / Wo) -> in-kernel
// LDG + cvt + swizzled STS ([k][n] fp16 tile, 256B rows) + ldmatrix.trans.
// A: AF32=1 -> fp32 LDG+cvt+STS (x);  AF32=0 -> fp16 cp.async (yh).
// EPI=0: fp32 store. EPI=1: per-row L2-normalize within 128-col tile, fp16.
// Stage: A tile 10240 B (80B x 128 rows) + B tile 8192 B (256B x 32 rows).
// ---------------------------------------------------------------------------
#define ATILE_B 10240
#define STAGE_B 18432
#define SMEM_GEMM (3 * STAGE_B)

template <int EPI, int AF32>
__global__ __launch_bounds__(256)
void gemm_mma(const void* __restrict__ Av, const float* __restrict__ Bf,
              void* __restrict__ Cv, int K, int lda, int ldb, int ldc)
{
    extern __shared__ char smem[];
    const uint32_t sbase = smem_u32(smem);
    const int tid = threadIdx.x;
    const int wid = tid >> 5, lane = tid & 31;
    const int wm = wid & 3, wn = wid >> 2;
    const int m0 = blockIdx.x * 128, n0 = blockIdx.y * 128;

    const __half* Ah = (const __half*)Av;
    const float*  Af = (const float*)Av;

    const int nc = K / 32;
    const int lr0 = tid >> 2, lc0 = tid & 3;
    const int lr1 = lr0 + 64;

    // ---- A loaders ----
    auto loadA16 = [&](int c) {              // fp16 cp.async path
        const int k0 = c * 32;
        const uint32_t sb = sbase + (uint32_t)(c % 3) * STAGE_B;
        cp16(sb + (uint32_t)(lr0 * 80 + lc0 * 16),
             Ah + (long long)(m0 + lr0) * lda + k0 + lc0 * 8);
        cp16(sb + (uint32_t)(lr1 * 80 + lc0 * 16),
             Ah + (long long)(m0 + lr1) * lda + k0 + lc0 * 8);
    };
    const int ar = tid >> 1;                 // fp32 path: row, k-half
    const int ac0 = (tid & 1) * 2;
    auto ldgcvtA = [&](int c, uint32_t* ra) {
        const int k0 = c * 32;
        #pragma unroll
        for (int j = 0; j < 2; j++) {
            const float4* g = reinterpret_cast<const float4*>(
                Af + (long long)(m0 + ar) * lda + k0 + (ac0 + j) * 8);
            float4 g0 = g[0], g1 = g[1];
            ra[j*4+0] = pkh(g0.x, g0.y);
            ra[j*4+1] = pkh(g0.z, g0.w);
            ra[j*4+2] = pkh(g1.x, g1.y);
            ra[j*4+3] = pkh(g1.z, g1.w);
        }
    };
    auto stsA = [&](int c, const uint32_t* ra) {
        const uint32_t so = (uint32_t)(c % 3) * STAGE_B;
        #pragma unroll
        for (int j = 0; j < 2; j++) {
            uint4 u = make_uint4(ra[j*4], ra[j*4+1], ra[j*4+2], ra[j*4+3]);
            *reinterpret_cast<uint4*>(smem + so + ar * 80 + (ac0 + j) * 16) = u;
        }
    };

    // ---- B loader: fp32 rows of W[k][n0..n0+127], cvt, swizzled STS ----
    auto ldgcvtB = [&](int c, uint32_t* rb) {
        const int k0 = c * 32;
        #pragma unroll
        for (int it = 0; it < 4; it++) {
            int i = tid + it * 256;
            int kk = i >> 5, f4 = i & 31;
            const float4* g = reinterpret_cast<const float4*>(
                Bf + (long long)(k0 + kk) * ldb + n0 + f4 * 4);
            float4 v = *g;
            rb[it*2]   = pkh(v.x, v.y);
            rb[it*2+1] = pkh(v.z, v.w);
        }
    };
    auto stsB = [&](int c, const uint32_t* rb) {
        const uint32_t so = (uint32_t)(c % 3) * STAGE_B + ATILE_B;
        #pragma unroll
        for (int it = 0; it < 4; it++) {
            int i = tid + it * 256;
            int kk = i >> 5, f4 = i & 31;
            uint32_t off = (uint32_t)(kk * 256 + f4 * 8);
            uint32_t sw = off ^ ((off >> 4) & 0x70u);
            uint2 u = make_uint2(rb[it*2], rb[it*2+1]);
            *reinterpret_cast<uint2*>(smem + so + sw) = u;
        }
    };

    // ---- fragment addresses ----
    const uint32_t arow = (uint32_t)((wm * 32 + (lane & 15)) * 80 + (lane >> 4) * 16);
    // B (trans): lane -> k-row (lane&15); n base = wn*64 halfs (128 B) + p*16
    const int brl = lane & 15;
    const uint32_t bconst = (uint32_t)(brl * 256);
    const uint32_t bnbase = (uint32_t)(wn * 128);           // FIX: warp n-column
    const uint32_t blow = (uint32_t)(((lane >> 4) << 3) * 2);
    const uint32_t bxor2 = (uint32_t)((brl & 7) << 4);

    float acc[2][8][4];
    #pragma unroll
    for (int i = 0; i < 2; i++)
        #pragma unroll
        for (int j = 0; j < 8; j++)
            #pragma unroll
            for (int q = 0; q < 4; q++) acc[i][j][q] = 0.0f;

    uint32_t ra[8], rb[8];
    // prologue: stages 0 and 1
    if (AF32) { ldgcvtA(0, ra); stsA(0, ra); } else { loadA16(0); }
    ldgcvtB(0, rb); stsB(0, rb);
    CP_COMMIT();
    if (AF32) { ldgcvtA(1, ra); stsA(1, ra); } else { loadA16(1); }
    ldgcvtB(1, rb); stsB(1, rb);
    CP_COMMIT();

    for (int c = 0; c < nc; c++) {
        if (c + 2 < nc) {                     // LDG early: hide behind MMAs
            if (AF32) ldgcvtA(c + 2, ra);
            ldgcvtB(c + 2, rb);
        }
        CP_WAIT(1);
        __syncthreads();

        const uint32_t sb = sbase + (uint32_t)(c % 3) * STAGE_B;
        const uint32_t sbB = sb + ATILE_B;
        #pragma unroll
        for (int kk = 0; kk < 2; kk++) {
            const uint32_t kbyte = (uint32_t)(kk * 32);
            uint32_t ah[2][4];
            #pragma unroll
            for (int mt = 0; mt < 2; mt++) {
                uint32_t ad = sb + arow + (uint32_t)(mt * 16 * 80) + kbyte;
                ldsm4(ah[mt][0], ah[mt][1], ah[mt][2], ah[mt][3], ad);
            }
            uint32_t bh[8][2];
            #pragma unroll
            for (int p = 0; p < 4; p++) {
                uint32_t bd = sbB + (uint32_t)(kk * 4096) + bconst
                            + ((bnbase + (uint32_t)(p * 32) + blow) ^ bxor2);
                ldsm4t(bh[2*p][0], bh[2*p][1], bh[2*p+1][0], bh[2*p+1][1], bd);
            }
            #pragma unroll
            for (int mt = 0; mt < 2; mt++)
                #pragma unroll
                for (int nt = 0; nt < 8; nt++)
                    mma_f16(acc[mt][nt], ah[mt], bh[nt]);
        }

        if (c + 2 < nc) {
            if (AF32) stsA(c + 2, ra); else loadA16(c + 2);
            stsB(c + 2, rb);
        }
        CP_COMMIT();
    }

    if (EPI == 0) {
        float* C = (float*)Cv;
        const int mb = m0 + wm * 32 + (lane >> 2);
        const int nb = n0 + wn * 64 + (lane & 3) * 2;
        #pragma unroll
        for (int mt = 0; mt < 2; mt++)
            #pragma unroll
            for (int nt = 0; nt < 8; nt++) {
                int m = mb + mt * 16, n = nb + nt * 8;
                float2 v0 = {acc[mt][nt][0], acc[mt][nt][1]};
                float2 v1 = {acc[mt][nt][2], acc[mt][nt][3]};
                *reinterpret_cast<float2*>(C + (long long)m * ldc + n) = v0;
                *reinterpret_cast<float2*>(C + (long long)(m + 8) * ldc + n) = v1;
            }
    } else {
        __half* C = (__half*)Cv;
        float p[4];
        #pragma unroll
        for (int i = 0; i < 4; i++) p[i] = 0.0f;
        #pragma unroll
        for (int mt = 0; mt < 2; mt++)
            #pragma unroll
            for (int nt = 0; nt < 8; nt++) {
                p[mt*2]   += acc[mt][nt][0]*acc[mt][nt][0] + acc[mt][nt][1]*acc[mt][nt][1];
                p[mt*2+1] += acc[mt][nt][2]*acc[mt][nt][2] + acc[mt][nt][3]*acc[mt][nt][3];
            }
        #pragma unroll
        for (int o = 1; o <= 2; o <<= 1)
            #pragma unroll
            for (int i = 0; i < 4; i++)
                p[i] += __shfl_xor_sync(0xFFFFFFFFu, p[i], o);
        __syncthreads();
        float* rs = reinterpret_cast<float*>(smem);
        const int rl = wm * 32 + (lane >> 2);
        if ((lane & 3) == 0) {
            rs[(rl +  0) * 2 + wn] = p[0];
            rs[(rl +  8) * 2 + wn] = p[1];
            rs[(rl + 16) * 2 + wn] = p[2];
            rs[(rl + 24) * 2 + wn] = p[3];
        }
        __syncthreads();
        float sc[4];
        #pragma unroll
        for (int i = 0; i < 4; i++) {
            int r = rl + (i & 1) * 8 + (i >> 1) * 16;
            sc[i] = rsqrtf(rs[r * 2] + rs[r * 2 + 1] + EPSN);
        }
        const int mb = m0 + wm * 32 + (lane >> 2);
        const int nb = n0 + wn * 64 + (lane & 3) * 2;
        #pragma unroll
        for (int mt = 0; mt < 2; mt++)
            #pragma unroll
            for (int nt = 0; nt < 8; nt++) {
                int m = mb + mt * 16, n = nb + nt * 8;
                uint32_t u0 = pkh(acc[mt][nt][0] * sc[mt*2],
                                  acc[mt][nt][1] * sc[mt*2]);
                uint32_t u1 = pkh(acc[mt][nt][2] * sc[mt*2+1],
                                  acc[mt][nt][3] * sc[mt*2+1]);
                *reinterpret_cast<uint32_t*>(C + (long long)m * ldc + n) = u0;
                *reinterpret_cast<uint32_t*>(C + (long long)(m + 8) * ldc + n) = u1;
            }
    }
}

// ---------------------------------------------------------------------------
// Transpose: out[c][r] = fp16(in[r][c])  (still used for V)
// ---------------------------------------------------------------------------
__global__ void transpose_h(const float* __restrict__ in, int ldi, long long inZ,
                            __half* __restrict__ oh, int ldo, long long outZ) {
    __shared__ float t[32][33];
    in += blockIdx.z * inZ;
    const long long ob = blockIdx.z * outZ;
    const int r0 = blockIdx.y * 32, c0 = blockIdx.x * 32;
    #pragma unroll
    for (int i = threadIdx.y; i < 32; i += 8)
        t[i][threadIdx.x] = in[(long long)(r0 + i) * ldi + c0 + threadIdx.x];
    __syncthreads();
    #pragma unroll
    for (int i = threadIdx.y; i < 32; i += 8) {
        long long o = ob + (long long)(c0 + i) * ldo + r0 + threadIdx.x;
        oh[o] = __float2half_rn(t[threadIdx.x][i]);
    }
}

// ---------------------------------------------------------------------------
// Row (128) L2-normalize + per-head scale, emit fp16 (keys)
// ---------------------------------------------------------------------------
__global__ void normalize_h(const float* __restrict__ src,
                            __half* __restrict__ hi,
                            const float* __restrict__ attn_scale, int nrows) {
    int row  = blockIdx.x * (blockDim.x >> 5) + (threadIdx.x >> 5);
    int lane = threadIdx.x & 31;
    if (row >= nrows) return;
    float4 v = reinterpret_cast<const float4*>(src + (size_t)row * HDIM)[lane];
    float ss = v.x * v.x + v.y * v.y + v.z * v.z + v.w * v.w;
    #pragma unroll
    for (int o = 16; o; o >>= 1) ss += __shfl_xor_sync(0xFFFFFFFFu, ss, o);
    float sc = rsqrtf(ss + EPSN) * attn_scale[row & (NHEADS - 1)];
    size_t off = (size_t)row * HDIM + lane * 4;
    *reinterpret_cast<uint32_t*>(hi + off)     = pkh(v.x * sc, v.y * sc);
    *reinterpret_cast<uint32_t*>(hi + off + 2) = pkh(v.z * sc, v.w * sc);
}

// ---------------------------------------------------------------------------
// Launch
// ---------------------------------------------------------------------------
extern "C" void kernel_launch(void* const* d_in, const int* in_sizes, int n_in,
                              void* d_out, int out_size) {
    const float* x     = (const float*)d_in[0];
    const float* Wq    = (const float*)d_in[1];
    const float* keys  = (const float*)d_in[2];
    const float* vals  = (const float*)d_in[3];
    const float* ascal = (const float*)d_in[4];
    const float* Wo    = (const float*)d_in[5];
    float* out = (float*)d_out;

    __half *qh, *kh, *vth, *yh;
    cudaGetSymbolAddress((void**)&qh, g_qh);
    cudaGetSymbolAddress((void**)&kh, g_kh);
    cudaGetSymbolAddress((void**)&vth, g_vth);
    cudaGetSymbolAddress((void**)&yh, g_yh);

    cudaFuncSetAttribute((const void*)gemm_mma<0,0>,
                         cudaFuncAttributeMaxDynamicSharedMemorySize, SMEM_GEMM);
    cudaFuncSetAttribute((const void*)gemm_mma<1,1>,
                         cudaFuncAttributeMaxDynamicSharedMemorySize, SMEM_GEMM);
    cudaFuncSetAttribute((const void*)attn_fused,
                         cudaFuncAttributeMaxDynamicSharedMemorySize, SMEM_ATTN);

    static cudaStream_t s1 = nullptr;
    static cudaEvent_t evF = nullptr, evJ = nullptr;
    if (!s1) {
        cudaStreamCreateWithFlags(&s1, cudaStreamNonBlocking);
        cudaEventCreateWithFlags(&evF, cudaEventDisableTiming);
        cudaEventCreateWithFlags(&evJ, cudaEventDisableTiming);
    }

    // fork: side stream does attn prep (hidden under Q-proj)
    cudaEventRecord(evF, 0);
    cudaStreamWaitEvent(s1, evF, 0);
    normalize_h<<<(NHID * NHEADS) / 8, 256, 0, s1>>>(keys, kh, ascal, NHID * NHEADS);
    transpose_h<<<dim3(HDIM / 32, NHID / 32, NHEADS), dim3(32, 8), 0, s1>>>(
        vals, DMODEL, (long long)HDIM, vth, NHID, (long long)HDIM * NHID);
    cudaEventRecord(evJ, s1);

    // main: Q-proj starts immediately (Wq transposed in-kernel via ldsm.trans)
    gemm_mma<1,1><<<dim3(S_LEN / 128, DMODEL / 128), 256, SMEM_GEMM>>>(
        x, Wq, qh, DMODEL, DMODEL, DMODEL, DMODEL);

    // join side stream, then attention
    cudaStreamWaitEvent(0, evJ, 0);
    attn_fused<<<dim3(S_LEN / 128, NHEADS), 256, SMEM_ATTN>>>(qh, kh, vth, yh);

    // O-proj (A = yh fp16 cp.async; B = raw Wo fp32, in-kernel transpose)
    gemm_mma<0,0><<<dim3(S_LEN / 128, DMODEL / 128), 256, SMEM_GEMM>>>(
        yh, Wo, out, DMODEL, DMODEL, DMODEL, DMODEL);
}

// round 13
// speedup vs baseline: 1.0749x; 1.0749x over previous
#include <cuda_runtime.h>
#include <cuda_fp16.h>
#include <stdint.h>

#define S_LEN   4096
#define DMODEL  1024
#define NHEADS  8
#define HDIM    128
#define NHID    2048
#define EPSN    1e-6f
#define CHUNK   64
#define NCHUNK  (NHID / CHUNK)

// ---------------------------------------------------------------------------
// Scratch (device globals — no allocations allowed)
// ---------------------------------------------------------------------------
__device__ __align__(16) __half g_wqt_h[(size_t)DMODEL * DMODEL];
__device__ __align__(16) __half g_wot_h[(size_t)DMODEL * DMODEL];
__device__ __align__(16) __half g_qh[(size_t)S_LEN * DMODEL];
__device__ __align__(16) __half g_kh[(size_t)NHID * NHEADS * HDIM];
__device__ __align__(16) __half g_vth[(size_t)NHEADS * HDIM * NHID];
__device__ __align__(16) __half g_yh[(size_t)S_LEN * DMODEL];

// ---------------------------------------------------------------------------
// PTX helpers (baseline sm_80+ only)
// ---------------------------------------------------------------------------
__device__ __forceinline__ uint32_t smem_u32(const void* p) {
    uint32_t a;
    asm("{ .reg .u64 t; cvta.to.shared.u64 t, %1; cvt.u32.u64 %0, t; }"
        : "=r"(a) : "l"(p));
    return a;
}
__device__ __forceinline__ void cp16(uint32_t s, const void* g) {
    asm volatile("cp.async.cg.shared.global [%0], [%1], 16;" :: "r"(s), "l"(g));
}
#define CP_COMMIT() asm volatile("cp.async.commit_group;" ::: "memory")
#define CP_WAIT(n)  asm volatile("cp.async.wait_group %0;" :: "n"(n) : "memory")

__device__ __forceinline__ void ldsm4(uint32_t& r0, uint32_t& r1,
                                      uint32_t& r2, uint32_t& r3, uint32_t a) {
    asm volatile("ldmatrix.sync.aligned.m8n8.x4.shared.b16 {%0,%1,%2,%3}, [%4];"
                 : "=r"(r0), "=r"(r1), "=r"(r2), "=r"(r3) : "r"(a));
}
__device__ __forceinline__ void mma_f16(float* d, const uint32_t* a, const uint32_t* b) {
    asm volatile(
        "mma.sync.aligned.m16n8k16.row.col.f32.f16.f16.f32 "
        "{%0,%1,%2,%3}, {%4,%5,%6,%7}, {%8,%9}, {%0,%1,%2,%3};"
        : "+f"(d[0]), "+f"(d[1]), "+f"(d[2]), "+f"(d[3])
        : "r"(a[0]), "r"(a[1]), "r"(a[2]), "r"(a[3]), "r"(b[0]), "r"(b[1]));
}
__device__ __forceinline__ uint32_t pkh(float x, float y) {
    __half2 h = __floats2half2_rn(x, y);
    return *reinterpret_cast<uint32_t*>(&h);
}
// SW64 swizzle: rows of 64B; XOR bits[4:5] with row bits[1:2]
__device__ __forceinline__ uint32_t sw64(uint32_t off) {
    return off ^ ((off >> 3) & 0x30u);
}

// ---------------------------------------------------------------------------
// Fused attention (fp16, all 1-term), SW64 layout, 2 CTAs/SM (round-9 proven).
// ---------------------------------------------------------------------------
#define SQ   0u
#define SK0  32768u
#define SK1  49152u
#define SV0  65536u
#define SV1  81920u
#define SMEM_ATTN 98304

__global__ __launch_bounds__(256, 2)
void attn_fused(const __half* __restrict__ qh,
                const __half* __restrict__ kh,
                const __half* __restrict__ vth,
                __half* __restrict__ yh)
{
    extern __shared__ char smem[];
    const uint32_t sb = smem_u32(smem);
    const int tid = threadIdx.x;
    const int w = tid >> 5, lane = tid & 31;
    const int h = blockIdx.y;
    const int qrow0 = blockIdx.x * 128;

    const __half* qhp = qh + (size_t)qrow0 * DMODEL + h * HDIM;
    const __half* khp = kh + h * HDIM;
    const __half* vhp = vth + (size_t)h * HDIM * NHID;

    #pragma unroll
    for (int it = 0; it < 8; it++) {
        int i = tid + it * 256;
        int s = i >> 9, r = (i >> 2) & 127, c16 = i & 3;
        uint32_t sa = sb + SQ + (uint32_t)(s * 8192) + sw64((uint32_t)(r * 64 + c16 * 16));
        cp16(sa, qhp + (size_t)r * DMODEL + s * 32 + c16 * 8);
    }
    CP_COMMIT();

    auto loadK = [&](int c) {
        const uint32_t kb = sb + ((c & 1) ? SK1 : SK0);
        const int j0 = c * CHUNK;
        #pragma unroll
        for (int it = 0; it < 4; it++) {
            int i = tid + it * 256;
            int s = i >> 8, r = (i >> 2) & 63, c16 = i & 3;
            uint32_t sa = kb + (uint32_t)(s * 4096) + sw64((uint32_t)(r * 64 + c16 * 16));
            cp16(sa, khp + (size_t)(j0 + r) * DMODEL + s * 32 + c16 * 8);
        }
    };
    auto loadV = [&](int c) {
        const uint32_t vb = sb + ((c & 1) ? SV1 : SV0);
        const int j0 = c * CHUNK;
        #pragma unroll
        for (int it = 0; it < 4; it++) {
            int i = tid + it * 256;
            int s = i >> 9, r = (i >> 2) & 127, c16 = i & 3;
            uint32_t sa = vb + (uint32_t)(s * 8192) + sw64((uint32_t)(r * 64 + c16 * 16));
            cp16(sa, vhp + (size_t)r * NHID + j0 + s * 32 + c16 * 8);
        }
    };

    loadK(0); loadV(0); CP_COMMIT();
    loadK(1); loadV(1); CP_COMMIT();

    const int row_a = w * 16 + (lane & 15);
    const uint32_t qrowpart = (uint32_t)(row_a * 64 + (lane >> 4) * 16);
    const uint32_t qxor = (uint32_t)((row_a & 6) << 3);
    const int row_b = ((lane >> 4) << 3) + (lane & 7);
    const uint32_t browpart = (uint32_t)(row_b * 64 + ((lane >> 3) & 1) * 16);
    const uint32_t bxor = (uint32_t)((row_b & 6) << 3);

    float Y[16][4];
    #pragma unroll
    for (int i = 0; i < 16; i++)
        #pragma unroll
        for (int j = 0; j < 4; j++) Y[i][j] = 0.0f;
    float l0 = 0.0f, l1 = 0.0f;

    for (int c = 0; c < NCHUNK; c++) {
        CP_WAIT(1);
        __syncthreads();

        const uint32_t kb = sb + ((c & 1) ? SK1 : SK0);
        float S[8][4];
        #pragma unroll
        for (int i = 0; i < 8; i++)
            #pragma unroll
            for (int j = 0; j < 4; j++) S[i][j] = 0.0f;

        #pragma unroll
        for (int kk = 0; kk < 8; kk++) {
            uint32_t kko = (uint32_t)((kk & 1) * 32);
            uint32_t qaddr = sb + SQ + (uint32_t)((kk >> 1) * 8192)
                           + ((qrowpart | kko) ^ qxor);
            uint32_t ah[4];
            ldsm4(ah[0], ah[1], ah[2], ah[3], qaddr);
            uint32_t bh[8][2];
            #pragma unroll
            for (int p = 0; p < 4; p++) {
                uint32_t ka = kb + (uint32_t)((kk >> 1) * 4096 + p * 1024)
                            + ((browpart | kko) ^ bxor);
                ldsm4(bh[2*p][0], bh[2*p][1], bh[2*p+1][0], bh[2*p+1][1], ka);
            }
            #pragma unroll
            for (int nt = 0; nt < 8; nt++)
                mma_f16(S[nt], ah, bh[nt]);
        }

        uint32_t pa[4][4];
        #pragma unroll
        for (int kk2 = 0; kk2 < 4; kk2++) {
            #pragma unroll
            for (int half = 0; half < 2; half++) {
                int nt = 2 * kk2 + half;
                float e0 = __expf(S[nt][0]);
                float e1 = __expf(S[nt][1]);
                float e2 = __expf(S[nt][2]);
                float e3 = __expf(S[nt][3]);
                l0 += e0 + e1;
                l1 += e2 + e3;
                pa[kk2][2*half]     = pkh(e0, e1);
                pa[kk2][2*half + 1] = pkh(e2, e3);
            }
        }

        const uint32_t vb = sb + ((c & 1) ? SV1 : SV0);
        #pragma unroll
        for (int kk2 = 0; kk2 < 4; kk2++) {
            uint32_t kko = (uint32_t)((kk2 & 1) * 32);
            #pragma unroll
            for (int p = 0; p < 8; p++) {
                uint32_t va = vb + (uint32_t)((kk2 >> 1) * 8192 + p * 1024)
                            + ((browpart | kko) ^ bxor);
                uint32_t vh[4];
                ldsm4(vh[0], vh[1], vh[2], vh[3], va);
                uint32_t b0[2] = {vh[0], vh[1]}, b1[2] = {vh[2], vh[3]};
                mma_f16(Y[2*p],     pa[kk2], b0);
                mma_f16(Y[2*p + 1], pa[kk2], b1);
            }
        }
        __syncthreads();

        if (c + 2 < NCHUNK) { loadK(c + 2); loadV(c + 2); }
        CP_COMMIT();
    }

    #pragma unroll
    for (int o = 1; o <= 2; o <<= 1) {
        l0 += __shfl_xor_sync(0xFFFFFFFFu, l0, o);
        l1 += __shfl_xor_sync(0xFFFFFFFFu, l1, o);
    }
    const float r0 = 1.0f / l0, r1 = 1.0f / l1;
    const int g = lane >> 2, colb = (lane & 3) * 2;
    #pragma unroll
    for (int nt = 0; nt < 16; nt++) {
        uint32_t h01 = pkh(Y[nt][0] * r0, Y[nt][1] * r0);
        uint32_t h23 = pkh(Y[nt][2] * r1, Y[nt][3] * r1);
        size_t o0 = (size_t)(qrow0 + w * 16 + g) * DMODEL + h * HDIM + nt * 8 + colb;
        *reinterpret_cast<uint32_t*>(yh + o0) = h01;
        *reinterpret_cast<uint32_t*>(yh + o0 + (size_t)8 * DMODEL) = h23;
    }
}

// ---------------------------------------------------------------------------
// 1-term fp16 HMMA GEMM, 3-stage, single barrier per iteration.
// AF32=1: A is fp32 in gmem -> LDG + cvt + STS (fused conversion).
// AF32=0: A is fp16 -> cp.async.
// EPI=0: fp32 store. EPI=1: per-row L2-normalize within 128-col tile, fp16.
// ---------------------------------------------------------------------------
#define STAGE_B 20480
#define TILE_B  10240
#define SMEM_GEMM (3 * STAGE_B)

template <int EPI, int AF32>
__global__ __launch_bounds__(256)
void gemm_mma(const void* __restrict__ Av, const __half* __restrict__ Bh,
              void* __restrict__ Cv, int K, int lda, int ldb, int ldc)
{
    extern __shared__ char smem[];
    const uint32_t sbase = smem_u32(smem);
    const int tid = threadIdx.x;
    const int wid = tid >> 5, lane = tid & 31;
    const int wm = wid & 3, wn = wid >> 2;
    const int m0 = blockIdx.x * 128, n0 = blockIdx.y * 128;

    const __half* Ah = (const __half*)Av;
    const float*  Af = (const float*)Av;

    const int nc = K / 32;
    const int lr0 = tid >> 2, lc0 = tid & 3;
    const int lr1 = lr0 + 64;

    // B loader (cp.async, both paths)
    auto loadB = [&](int c) {
        const int k0 = c * 32;
        const uint32_t sb = sbase + (uint32_t)(c % 3) * STAGE_B;
        cp16(sb + TILE_B + (uint32_t)(lr0 * 80 + lc0 * 16),
             Bh + (long long)(n0 + lr0) * ldb + k0 + lc0 * 8);
        cp16(sb + TILE_B + (uint32_t)(lr1 * 80 + lc0 * 16),
             Bh + (long long)(n0 + lr1) * ldb + k0 + lc0 * 8);
    };
    // A loader, fp16 cp.async path
    auto loadA16 = [&](int c) {
        const int k0 = c * 32;
        const uint32_t sb = sbase + (uint32_t)(c % 3) * STAGE_B;
        cp16(sb + (uint32_t)(lr0 * 80 + lc0 * 16),
             Ah + (long long)(m0 + lr0) * lda + k0 + lc0 * 8);
        cp16(sb + (uint32_t)(lr1 * 80 + lc0 * 16),
             Ah + (long long)(m0 + lr1) * lda + k0 + lc0 * 8);
    };
    // A loader, fp32 LDG path
    const int ar = tid >> 1;
    const int ac0 = (tid & 1) * 2;
    auto ldgA = [&](int c, float4* v) {
        const int k0 = c * 32;
        #pragma unroll
        for (int j = 0; j < 2; j++) {
            const float4* g = reinterpret_cast<const float4*>(
                Af + (long long)(m0 + ar) * lda + k0 + (ac0 + j) * 8);
            v[j * 2]     = g[0];
            v[j * 2 + 1] = g[1];
        }
    };
    auto stsA = [&](int c, const float4* v) {
        const uint32_t so = (uint32_t)(c % 3) * STAGE_B;
        #pragma unroll
        for (int j = 0; j < 2; j++) {
            uint4 u;
            u.x = pkh(v[j*2].x,   v[j*2].y);
            u.y = pkh(v[j*2].z,   v[j*2].w);
            u.z = pkh(v[j*2+1].x, v[j*2+1].y);
            u.w = pkh(v[j*2+1].z, v[j*2+1].w);
            *reinterpret_cast<uint4*>(smem + so + ar * 80 + (ac0 + j) * 16) = u;
        }
    };

    const uint32_t arow = (uint32_t)((wm * 32 + (lane & 15)) * 80 + (lane >> 4) * 16);
    const uint32_t brow = (uint32_t)((wn * 64 + ((lane >> 4) << 3) + (lane & 7)) * 80
                                     + ((lane >> 3) & 1) * 16);

    float acc[2][8][4];
    #pragma unroll
    for (int i = 0; i < 2; i++)
        #pragma unroll
        for (int j = 0; j < 8; j++)
            #pragma unroll
            for (int q = 0; q < 4; q++) acc[i][j][q] = 0.0f;

    float4 va[4];
    if (AF32) { ldgA(0, va); stsA(0, va); } else { loadA16(0); }
    loadB(0); CP_COMMIT();
    if (AF32) { ldgA(1, va); stsA(1, va); } else { loadA16(1); }
    loadB(1); CP_COMMIT();

    for (int c = 0; c < nc; c++) {
        if (AF32 && c + 2 < nc) ldgA(c + 2, va);
        CP_WAIT(1);
        __syncthreads();

        const uint32_t sb = sbase + (uint32_t)(c % 3) * STAGE_B;
        #pragma unroll
        for (int kk = 0; kk < 2; kk++) {
            const uint32_t kbyte = (uint32_t)(kk * 32);
            uint32_t ah[2][4];
            #pragma unroll
            for (int mt = 0; mt < 2; mt++) {
                uint32_t ad = sb + arow + (uint32_t)(mt * 16 * 80) + kbyte;
                ldsm4(ah[mt][0], ah[mt][1], ah[mt][2], ah[mt][3], ad);
            }
            uint32_t bh[8][2];
            #pragma unroll
            for (int p = 0; p < 4; p++) {
                uint32_t bd = sb + TILE_B + brow + (uint32_t)(p * 16 * 80) + kbyte;
                ldsm4(bh[2*p][0], bh[2*p][1], bh[2*p+1][0], bh[2*p+1][1], bd);
            }
            #pragma unroll
            for (int mt = 0; mt < 2; mt++)
                #pragma unroll
                for (int nt = 0; nt < 8; nt++)
                    mma_f16(acc[mt][nt], ah[mt], bh[nt]);
        }

        if (c + 2 < nc) {
            if (AF32) stsA(c + 2, va); else loadA16(c + 2);
            loadB(c + 2);
        }
        CP_COMMIT();
    }

    if (EPI == 0) {
        float* C = (float*)Cv;
        const int mb = m0 + wm * 32 + (lane >> 2);
        const int nb = n0 + wn * 64 + (lane & 3) * 2;
        #pragma unroll
        for (int mt = 0; mt < 2; mt++)
            #pragma unroll
            for (int nt = 0; nt < 8; nt++) {
                int m = mb + mt * 16, n = nb + nt * 8;
                float2 v0 = {acc[mt][nt][0], acc[mt][nt][1]};
                float2 v1 = {acc[mt][nt][2], acc[mt][nt][3]};
                *reinterpret_cast<float2*>(C + (long long)m * ldc + n) = v0;
                *reinterpret_cast<float2*>(C + (long long)(m + 8) * ldc + n) = v1;
            }
    } else {
        __half* C = (__half*)Cv;
        float p[4];
        #pragma unroll
        for (int i = 0; i < 4; i++) p[i] = 0.0f;
        #pragma unroll
        for (int mt = 0; mt < 2; mt++)
            #pragma unroll
            for (int nt = 0; nt < 8; nt++) {
                p[mt*2]   += acc[mt][nt][0]*acc[mt][nt][0] + acc[mt][nt][1]*acc[mt][nt][1];
                p[mt*2+1] += acc[mt][nt][2]*acc[mt][nt][2] + acc[mt][nt][3]*acc[mt][nt][3];
            }
        #pragma unroll
        for (int o = 1; o <= 2; o <<= 1)
            #pragma unroll
            for (int i = 0; i < 4; i++)
                p[i] += __shfl_xor_sync(0xFFFFFFFFu, p[i], o);
        __syncthreads();
        float* rs = reinterpret_cast<float*>(smem);
        const int rl = wm * 32 + (lane >> 2);
        if ((lane & 3) == 0) {
            rs[(rl +  0) * 2 + wn] = p[0];
            rs[(rl +  8) * 2 + wn] = p[1];
            rs[(rl + 16) * 2 + wn] = p[2];
            rs[(rl + 24) * 2 + wn] = p[3];
        }
        __syncthreads();
        float sc[4];
        #pragma unroll
        for (int i = 0; i < 4; i++) {
            int r = rl + (i & 1) * 8 + (i >> 1) * 16;
            sc[i] = rsqrtf(rs[r * 2] + rs[r * 2 + 1] + EPSN);
        }
        const int mb = m0 + wm * 32 + (lane >> 2);
        const int nb = n0 + wn * 64 + (lane & 3) * 2;
        #pragma unroll
        for (int mt = 0; mt < 2; mt++)
            #pragma unroll
            for (int nt = 0; nt < 8; nt++) {
                int m = mb + mt * 16, n = nb + nt * 8;
                uint32_t u0 = pkh(acc[mt][nt][0] * sc[mt*2],
                                  acc[mt][nt][1] * sc[mt*2]);
                uint32_t u1 = pkh(acc[mt][nt][2] * sc[mt*2+1],
                                  acc[mt][nt][3] * sc[mt*2+1]);
                *reinterpret_cast<uint32_t*>(C + (long long)m * ldc + n) = u0;
                *reinterpret_cast<uint32_t*>(C + (long long)(m + 8) * ldc + n) = u1;
            }
    }
}

// ---------------------------------------------------------------------------
// Transpose: out[c][r] = fp16(in[r][c])
// ---------------------------------------------------------------------------
__global__ void transpose_h(const float* __restrict__ in, int ldi, long long inZ,
                            __half* __restrict__ oh, int ldo, long long outZ) {
    __shared__ float t[32][33];
    in += blockIdx.z * inZ;
    const long long ob = blockIdx.z * outZ;
    const int r0 = blockIdx.y * 32, c0 = blockIdx.x * 32;
    #pragma unroll
    for (int i = threadIdx.y; i < 32; i += 8)
        t[i][threadIdx.x] = in[(long long)(r0 + i) * ldi + c0 + threadIdx.x];
    __syncthreads();
    #pragma unroll
    for (int i = threadIdx.y; i < 32; i += 8) {
        long long o = ob + (long long)(c0 + i) * ldo + r0 + threadIdx.x;
        oh[o] = __float2half_rn(t[threadIdx.x][i]);
    }
}

// ---------------------------------------------------------------------------
// Row (128) L2-normalize + per-head scale, emit fp16 (keys)
// ---------------------------------------------------------------------------
__global__ void normalize_h(const float* __restrict__ src,
                            __half* __restrict__ hi,
                            const float* __restrict__ attn_scale, int nrows) {
    int row  = blockIdx.x * (blockDim.x >> 5) + (threadIdx.x >> 5);
    int lane = threadIdx.x & 31;
    if (row >= nrows) return;
    float4 v = reinterpret_cast<const float4*>(src + (size_t)row * HDIM)[lane];
    float ss = v.x * v.x + v.y * v.y + v.z * v.z + v.w * v.w;
    #pragma unroll
    for (int o = 16; o; o >>= 1) ss += __shfl_xor_sync(0xFFFFFFFFu, ss, o);
    float sc = rsqrtf(ss + EPSN) * attn_scale[row & (NHEADS - 1)];
    size_t off = (size_t)row * HDIM + lane * 4;
    *reinterpret_cast<uint32_t*>(hi + off)     = pkh(v.x * sc, v.y * sc);
    *reinterpret_cast<uint32_t*>(hi + off + 2) = pkh(v.z * sc, v.w * sc);
}

// ---------------------------------------------------------------------------
// Launch (side stream prep; fork/join via events)
// ---------------------------------------------------------------------------
extern "C" void kernel_launch(void* const* d_in, const int* in_sizes, int n_in,
                              void* d_out, int out_size) {
    const float* x     = (const float*)d_in[0];
    const float* Wq    = (const float*)d_in[1];
    const float* keys  = (const float*)d_in[2];
    const float* vals  = (const float*)d_in[3];
    const float* ascal = (const float*)d_in[4];
    const float* Wo    = (const float*)d_in[5];
    float* out = (float*)d_out;

    __half *wqh, *woh, *qh, *kh, *vth, *yh;
    cudaGetSymbolAddress((void**)&wqh, g_wqt_h);
    cudaGetSymbolAddress((void**)&woh, g_wot_h);
    cudaGetSymbolAddress((void**)&qh, g_qh);
    cudaGetSymbolAddress((void**)&kh, g_kh);
    cudaGetSymbolAddress((void**)&vth, g_vth);
    cudaGetSymbolAddress((void**)&yh, g_yh);

    cudaFuncSetAttribute((const void*)gemm_mma<0,0>,
                         cudaFuncAttributeMaxDynamicSharedMemorySize, SMEM_GEMM);
    cudaFuncSetAttribute((const void*)gemm_mma<1,1>,
                         cudaFuncAttributeMaxDynamicSharedMemorySize, SMEM_GEMM);
    cudaFuncSetAttribute((const void*)attn_fused,
                         cudaFuncAttributeMaxDynamicSharedMemorySize, SMEM_ATTN);

    static cudaStream_t s1 = nullptr;
    static cudaEvent_t evF = nullptr, evW = nullptr, evJ = nullptr;
    if (!s1) {
        cudaStreamCreateWithFlags(&s1, cudaStreamNonBlocking);
        cudaEventCreateWithFlags(&evF, cudaEventDisableTiming);
        cudaEventCreateWithFlags(&evW, cudaEventDisableTiming);
        cudaEventCreateWithFlags(&evJ, cudaEventDisableTiming);
    }

    // fork: side stream — WqT first (gates Q-proj), then hidden prep
    cudaEventRecord(evF, 0);
    cudaStreamWaitEvent(s1, evF, 0);
    transpose_h<<<dim3(32, 32, 1), dim3(32, 8), 0, s1>>>(Wq, DMODEL, 0, wqh, DMODEL, 0);
    cudaEventRecord(evW, s1);
    normalize_h<<<(NHID * NHEADS) / 8, 256, 0, s1>>>(keys, kh, ascal, NHID * NHEADS);
    transpose_h<<<dim3(HDIM / 32, NHID / 32, NHEADS), dim3(32, 8), 0, s1>>>(
        vals, DMODEL, (long long)HDIM, vth, NHID, (long long)HDIM * NHID);
    transpose_h<<<dim3(32, 32, 1), dim3(32, 8), 0, s1>>>(Wo, DMODEL, 0, woh, DMODEL, 0);
    cudaEventRecord(evJ, s1);

    // main: Q-proj with fused fp32->fp16 conversion of x and fused q-normalize
    cudaStreamWaitEvent(0, evW, 0);
    gemm_mma<1,1><<<dim3(S_LEN / 128, DMODEL / 128), 256, SMEM_GEMM>>>(
        x, wqh, qh, DMODEL, DMODEL, DMODEL, DMODEL);

    // join side stream, then attention
    cudaStreamWaitEvent(0, evJ, 0);
    attn_fused<<<dim3(S_LEN / 128, NHEADS), 256, SMEM_ATTN>>>(qh, kh, vth, yh);

    // O-proj (1-term) -> fp32 out
    gemm_mma<0,0><<<dim3(S_LEN / 128, DMODEL / 128), 256, SMEM_GEMM>>>(
        yh, woh, out, DMODEL, DMODEL, DMODEL, DMODEL);
}

// round 14
// speedup vs baseline: 1.0772x; 1.0022x over previous
#include <cuda_runtime.h>
#include <cuda_fp16.h>
#include <stdint.h>

#define S_LEN   4096
#define DMODEL  1024
#define NHEADS  8
#define HDIM    128
#define NHID    2048
#define EPSN    1e-6f
#define CHUNK   64
#define NCHUNK  (NHID / CHUNK)

// ---------------------------------------------------------------------------
// Scratch (device globals — no allocations allowed)
// ---------------------------------------------------------------------------
__device__ __align__(16) __half g_wqt_h[(size_t)DMODEL * DMODEL];
__device__ __align__(16) __half g_wot_h[(size_t)DMODEL * DMODEL];
__device__ __align__(16) __half g_qh[(size_t)S_LEN * DMODEL];
__device__ __align__(16) __half g_kh[(size_t)NHID * NHEADS * HDIM];
__device__ __align__(16) __half g_vth[(size_t)NHEADS * HDIM * NHID];
__device__ __align__(16) __half g_yh[(size_t)S_LEN * DMODEL];

// ---------------------------------------------------------------------------
// PTX helpers (baseline sm_80+ only)
// ---------------------------------------------------------------------------
__device__ __forceinline__ uint32_t smem_u32(const void* p) {
    uint32_t a;
    asm("{ .reg .u64 t; cvta.to.shared.u64 t, %1; cvt.u32.u64 %0, t; }"
        : "=r"(a) : "l"(p));
    return a;
}
__device__ __forceinline__ void cp16(uint32_t s, const void* g) {
    asm volatile("cp.async.cg.shared.global [%0], [%1], 16;" :: "r"(s), "l"(g));
}
#define CP_COMMIT() asm volatile("cp.async.commit_group;" ::: "memory")
#define CP_WAIT(n)  asm volatile("cp.async.wait_group %0;" :: "n"(n) : "memory")

__device__ __forceinline__ void ldsm4(uint32_t& r0, uint32_t& r1,
                                      uint32_t& r2, uint32_t& r3, uint32_t a) {
    asm volatile("ldmatrix.sync.aligned.m8n8.x4.shared.b16 {%0,%1,%2,%3}, [%4];"
                 : "=r"(r0), "=r"(r1), "=r"(r2), "=r"(r3) : "r"(a));
}
__device__ __forceinline__ void mma_f16(float* d, const uint32_t* a, const uint32_t* b) {
    asm volatile(
        "mma.sync.aligned.m16n8k16.row.col.f32.f16.f16.f32 "
        "{%0,%1,%2,%3}, {%4,%5,%6,%7}, {%8,%9}, {%0,%1,%2,%3};"
        : "+f"(d[0]), "+f"(d[1]), "+f"(d[2]), "+f"(d[3])
        : "r"(a[0]), "r"(a[1]), "r"(a[2]), "r"(a[3]), "r"(b[0]), "r"(b[1]));
}
__device__ __forceinline__ uint32_t pkh(float x, float y) {
    __half2 h = __floats2half2_rn(x, y);
    return *reinterpret_cast<uint32_t*>(&h);
}
// SW64 swizzle: rows of 64B; XOR bits[4:5] with row bits[1:2]
__device__ __forceinline__ uint32_t sw64(uint32_t off) {
    return off ^ ((off >> 3) & 0x30u);
}

// ---------------------------------------------------------------------------
// Fused attention (fp16, all 1-term), SW64 layout, 2 CTAs/SM (round-9 proven).
// ---------------------------------------------------------------------------
#define SQ   0u
#define SK0  32768u
#define SK1  49152u
#define SV0  65536u
#define SV1  81920u
#define SMEM_ATTN 98304

__global__ __launch_bounds__(256, 2)
void attn_fused(const __half* __restrict__ qh,
                const __half* __restrict__ kh,
                const __half* __restrict__ vth,
                __half* __restrict__ yh)
{
    extern __shared__ char smem[];
    const uint32_t sb = smem_u32(smem);
    const int tid = threadIdx.x;
    const int w = tid >> 5, lane = tid & 31;
    const int h = blockIdx.y;
    const int qrow0 = blockIdx.x * 128;

    const __half* qhp = qh + (size_t)qrow0 * DMODEL + h * HDIM;
    const __half* khp = kh + h * HDIM;
    const __half* vhp = vth + (size_t)h * HDIM * NHID;

    #pragma unroll
    for (int it = 0; it < 8; it++) {
        int i = tid + it * 256;
        int s = i >> 9, r = (i >> 2) & 127, c16 = i & 3;
        uint32_t sa = sb + SQ + (uint32_t)(s * 8192) + sw64((uint32_t)(r * 64 + c16 * 16));
        cp16(sa, qhp + (size_t)r * DMODEL + s * 32 + c16 * 8);
    }
    CP_COMMIT();

    auto loadK = [&](int c) {
        const uint32_t kb = sb + ((c & 1) ? SK1 : SK0);
        const int j0 = c * CHUNK;
        #pragma unroll
        for (int it = 0; it < 4; it++) {
            int i = tid + it * 256;
            int s = i >> 8, r = (i >> 2) & 63, c16 = i & 3;
            uint32_t sa = kb + (uint32_t)(s * 4096) + sw64((uint32_t)(r * 64 + c16 * 16));
            cp16(sa, khp + (size_t)(j0 + r) * DMODEL + s * 32 + c16 * 8);
        }
    };
    auto loadV = [&](int c) {
        const uint32_t vb = sb + ((c & 1) ? SV1 : SV0);
        const int j0 = c * CHUNK;
        #pragma unroll
        for (int it = 0; it < 4; it++) {
            int i = tid + it * 256;
            int s = i >> 9, r = (i >> 2) & 127, c16 = i & 3;
            uint32_t sa = vb + (uint32_t)(s * 8192) + sw64((uint32_t)(r * 64 + c16 * 16));
            cp16(sa, vhp + (size_t)r * NHID + j0 + s * 32 + c16 * 8);
        }
    };

    loadK(0); loadV(0); CP_COMMIT();
    loadK(1); loadV(1); CP_COMMIT();

    const int row_a = w * 16 + (lane & 15);
    const uint32_t qrowpart = (uint32_t)(row_a * 64 + (lane >> 4) * 16);
    const uint32_t qxor = (uint32_t)((row_a & 6) << 3);
    const int row_b = ((lane >> 4) << 3) + (lane & 7);
    const uint32_t browpart = (uint32_t)(row_b * 64 + ((lane >> 3) & 1) * 16);
    const uint32_t bxor = (uint32_t)((row_b & 6) << 3);

    float Y[16][4];
    #pragma unroll
    for (int i = 0; i < 16; i++)
        #pragma unroll
        for (int j = 0; j < 4; j++) Y[i][j] = 0.0f;
    float l0 = 0.0f, l1 = 0.0f;

    for (int c = 0; c < NCHUNK; c++) {
        CP_WAIT(1);
        __syncthreads();

        const uint32_t kb = sb + ((c & 1) ? SK1 : SK0);
        float S[8][4];
        #pragma unroll
        for (int i = 0; i < 8; i++)
            #pragma unroll
            for (int j = 0; j < 4; j++) S[i][j] = 0.0f;

        #pragma unroll
        for (int kk = 0; kk < 8; kk++) {
            uint32_t kko = (uint32_t)((kk & 1) * 32);
            uint32_t qaddr = sb + SQ + (uint32_t)((kk >> 1) * 8192)
                           + ((qrowpart | kko) ^ qxor);
            uint32_t ah[4];
            ldsm4(ah[0], ah[1], ah[2], ah[3], qaddr);
            uint32_t bh[8][2];
            #pragma unroll
            for (int p = 0; p < 4; p++) {
                uint32_t ka = kb + (uint32_t)((kk >> 1) * 4096 + p * 1024)
                            + ((browpart | kko) ^ bxor);
                ldsm4(bh[2*p][0], bh[2*p][1], bh[2*p+1][0], bh[2*p+1][1], ka);
            }
            #pragma unroll
            for (int nt = 0; nt < 8; nt++)
                mma_f16(S[nt], ah, bh[nt]);
        }

        uint32_t pa[4][4];
        #pragma unroll
        for (int kk2 = 0; kk2 < 4; kk2++) {
            #pragma unroll
            for (int half = 0; half < 2; half++) {
                int nt = 2 * kk2 + half;
                float e0 = __expf(S[nt][0]);
                float e1 = __expf(S[nt][1]);
                float e2 = __expf(S[nt][2]);
                float e3 = __expf(S[nt][3]);
                l0 += e0 + e1;
                l1 += e2 + e3;
                pa[kk2][2*half]     = pkh(e0, e1);
                pa[kk2][2*half + 1] = pkh(e2, e3);
            }
        }

        const uint32_t vb = sb + ((c & 1) ? SV1 : SV0);
        #pragma unroll
        for (int kk2 = 0; kk2 < 4; kk2++) {
            uint32_t kko = (uint32_t)((kk2 & 1) * 32);
            #pragma unroll
            for (int p = 0; p < 8; p++) {
                uint32_t va = vb + (uint32_t)((kk2 >> 1) * 8192 + p * 1024)
                            + ((browpart | kko) ^ bxor);
                uint32_t vh[4];
                ldsm4(vh[0], vh[1], vh[2], vh[3], va);
                uint32_t b0[2] = {vh[0], vh[1]}, b1[2] = {vh[2], vh[3]};
                mma_f16(Y[2*p],     pa[kk2], b0);
                mma_f16(Y[2*p + 1], pa[kk2], b1);
            }
        }
        __syncthreads();

        if (c + 2 < NCHUNK) { loadK(c + 2); loadV(c + 2); }
        CP_COMMIT();
    }

    #pragma unroll
    for (int o = 1; o <= 2; o <<= 1) {
        l0 += __shfl_xor_sync(0xFFFFFFFFu, l0, o);
        l1 += __shfl_xor_sync(0xFFFFFFFFu, l1, o);
    }
    const float r0 = 1.0f / l0, r1 = 1.0f / l1;
    const int g = lane >> 2, colb = (lane & 3) * 2;
    #pragma unroll
    for (int nt = 0; nt < 16; nt++) {
        uint32_t h01 = pkh(Y[nt][0] * r0, Y[nt][1] * r0);
        uint32_t h23 = pkh(Y[nt][2] * r1, Y[nt][3] * r1);
        size_t o0 = (size_t)(qrow0 + w * 16 + g) * DMODEL + h * HDIM + nt * 8 + colb;
        *reinterpret_cast<uint32_t*>(yh + o0) = h01;
        *reinterpret_cast<uint32_t*>(yh + o0 + (size_t)8 * DMODEL) = h23;
    }
}

// ---------------------------------------------------------------------------
// 1-term fp16 HMMA GEMM, 3-stage, single barrier per iteration, 2 CTAs/SM.
// AF32=1: A is fp32 in gmem -> LDG + cvt + STS (fused conversion).
// AF32=0: A is fp16 -> cp.async.
// EPI=0: fp32 store. EPI=1: per-row L2-normalize within 128-col tile, fp16.
// ---------------------------------------------------------------------------
#define STAGE_B 20480
#define TILE_B  10240
#define SMEM_GEMM (3 * STAGE_B)

template <int EPI, int AF32>
__global__ __launch_bounds__(256, 2)
void gemm_mma(const void* __restrict__ Av, const __half* __restrict__ Bh,
              void* __restrict__ Cv, int K, int lda, int ldb, int ldc)
{
    extern __shared__ char smem[];
    const uint32_t sbase = smem_u32(smem);
    const int tid = threadIdx.x;
    const int wid = tid >> 5, lane = tid & 31;
    const int wm = wid & 3, wn = wid >> 2;
    const int m0 = blockIdx.x * 128, n0 = blockIdx.y * 128;

    const __half* Ah = (const __half*)Av;
    const float*  Af = (const float*)Av;

    const int nc = K / 32;
    const int lr0 = tid >> 2, lc0 = tid & 3;
    const int lr1 = lr0 + 64;

    // B loader (cp.async, both paths)
    auto loadB = [&](int c) {
        const int k0 = c * 32;
        const uint32_t sb = sbase + (uint32_t)(c % 3) * STAGE_B;
        cp16(sb + TILE_B + (uint32_t)(lr0 * 80 + lc0 * 16),
             Bh + (long long)(n0 + lr0) * ldb + k0 + lc0 * 8);
        cp16(sb + TILE_B + (uint32_t)(lr1 * 80 + lc0 * 16),
             Bh + (long long)(n0 + lr1) * ldb + k0 + lc0 * 8);
    };
    // A loader, fp16 cp.async path
    auto loadA16 = [&](int c) {
        const int k0 = c * 32;
        const uint32_t sb = sbase + (uint32_t)(c % 3) * STAGE_B;
        cp16(sb + (uint32_t)(lr0 * 80 + lc0 * 16),
             Ah + (long long)(m0 + lr0) * lda + k0 + lc0 * 8);
        cp16(sb + (uint32_t)(lr1 * 80 + lc0 * 16),
             Ah + (long long)(m0 + lr1) * lda + k0 + lc0 * 8);
    };
    // A loader, fp32 LDG path
    const int ar = tid >> 1;
    const int ac0 = (tid & 1) * 2;
    auto ldgA = [&](int c, float4* v) {
        const int k0 = c * 32;
        #pragma unroll
        for (int j = 0; j < 2; j++) {
            const float4* g = reinterpret_cast<const float4*>(
                Af + (long long)(m0 + ar) * lda + k0 + (ac0 + j) * 8);
            v[j * 2]     = g[0];
            v[j * 2 + 1] = g[1];
        }
    };
    auto stsA = [&](int c, const float4* v) {
        const uint32_t so = (uint32_t)(c % 3) * STAGE_B;
        #pragma unroll
        for (int j = 0; j < 2; j++) {
            uint4 u;
            u.x = pkh(v[j*2].x,   v[j*2].y);
            u.y = pkh(v[j*2].z,   v[j*2].w);
            u.z = pkh(v[j*2+1].x, v[j*2+1].y);
            u.w = pkh(v[j*2+1].z, v[j*2+1].w);
            *reinterpret_cast<uint4*>(smem + so + ar * 80 + (ac0 + j) * 16) = u;
        }
    };

    const uint32_t arow = (uint32_t)((wm * 32 + (lane & 15)) * 80 + (lane >> 4) * 16);
    const uint32_t brow = (uint32_t)((wn * 64 + ((lane >> 4) << 3) + (lane & 7)) * 80
                                     + ((lane >> 3) & 1) * 16);

    float acc[2][8][4];
    #pragma unroll
    for (int i = 0; i < 2; i++)
        #pragma unroll
        for (int j = 0; j < 8; j++)
            #pragma unroll
            for (int q = 0; q < 4; q++) acc[i][j][q] = 0.0f;

    float4 va[4];
    if (AF32) { ldgA(0, va); stsA(0, va); } else { loadA16(0); }
    loadB(0); CP_COMMIT();
    if (AF32) { ldgA(1, va); stsA(1, va); } else { loadA16(1); }
    loadB(1); CP_COMMIT();

    for (int c = 0; c < nc; c++) {
        if (AF32 && c + 2 < nc) ldgA(c + 2, va);
        CP_WAIT(1);
        __syncthreads();

        const uint32_t sb = sbase + (uint32_t)(c % 3) * STAGE_B;
        #pragma unroll
        for (int kk = 0; kk < 2; kk++) {
            const uint32_t kbyte = (uint32_t)(kk * 32);
            uint32_t ah[2][4];
            #pragma unroll
            for (int mt = 0; mt < 2; mt++) {
                uint32_t ad = sb + arow + (uint32_t)(mt * 16 * 80) + kbyte;
                ldsm4(ah[mt][0], ah[mt][1], ah[mt][2], ah[mt][3], ad);
            }
            uint32_t bh[8][2];
            #pragma unroll
            for (int p = 0; p < 4; p++) {
                uint32_t bd = sb + TILE_B + brow + (uint32_t)(p * 16 * 80) + kbyte;
                ldsm4(bh[2*p][0], bh[2*p][1], bh[2*p+1][0], bh[2*p+1][1], bd);
            }
            #pragma unroll
            for (int mt = 0; mt < 2; mt++)
                #pragma unroll
                for (int nt = 0; nt < 8; nt++)
                    mma_f16(acc[mt][nt], ah[mt], bh[nt]);
        }

        if (c + 2 < nc) {
            if (AF32) stsA(c + 2, va); else loadA16(c + 2);
            loadB(c + 2);
        }
        CP_COMMIT();
    }

    if (EPI == 0) {
        float* C = (float*)Cv;
        const int mb = m0 + wm * 32 + (lane >> 2);
        const int nb = n0 + wn * 64 + (lane & 3) * 2;
        #pragma unroll
        for (int mt = 0; mt < 2; mt++)
            #pragma unroll
            for (int nt = 0; nt < 8; nt++) {
                int m = mb + mt * 16, n = nb + nt * 8;
                float2 v0 = {acc[mt][nt][0], acc[mt][nt][1]};
                float2 v1 = {acc[mt][nt][2], acc[mt][nt][3]};
                *reinterpret_cast<float2*>(C + (long long)m * ldc + n) = v0;
                *reinterpret_cast<float2*>(C + (long long)(m + 8) * ldc + n) = v1;
            }
    } else {
        __half* C = (__half*)Cv;
        float p[4];
        #pragma unroll
        for (int i = 0; i < 4; i++) p[i] = 0.0f;
        #pragma unroll
        for (int mt = 0; mt < 2; mt++)
            #pragma unroll
            for (int nt = 0; nt < 8; nt++) {
                p[mt*2]   += acc[mt][nt][0]*acc[mt][nt][0] + acc[mt][nt][1]*acc[mt][nt][1];
                p[mt*2+1] += acc[mt][nt][2]*acc[mt][nt][2] + acc[mt][nt][3]*acc[mt][nt][3];
            }
        #pragma unroll
        for (int o = 1; o <= 2; o <<= 1)
            #pragma unroll
            for (int i = 0; i < 4; i++)
                p[i] += __shfl_xor_sync(0xFFFFFFFFu, p[i], o);
        __syncthreads();
        float* rs = reinterpret_cast<float*>(smem);
        const int rl = wm * 32 + (lane >> 2);
        if ((lane & 3) == 0) {
            rs[(rl +  0) * 2 + wn] = p[0];
            rs[(rl +  8) * 2 + wn] = p[1];
            rs[(rl + 16) * 2 + wn] = p[2];
            rs[(rl + 24) * 2 + wn] = p[3];
        }
        __syncthreads();
        float sc[4];
        #pragma unroll
        for (int i = 0; i < 4; i++) {
            int r = rl + (i & 1) * 8 + (i >> 1) * 16;
            sc[i] = rsqrtf(rs[r * 2] + rs[r * 2 + 1] + EPSN);
        }
        const int mb = m0 + wm * 32 + (lane >> 2);
        const int nb = n0 + wn * 64 + (lane & 3) * 2;
        #pragma unroll
        for (int mt = 0; mt < 2; mt++)
            #pragma unroll
            for (int nt = 0; nt < 8; nt++) {
                int m = mb + mt * 16, n = nb + nt * 8;
                uint32_t u0 = pkh(acc[mt][nt][0] * sc[mt*2],
                                  acc[mt][nt][1] * sc[mt*2]);
                uint32_t u1 = pkh(acc[mt][nt][2] * sc[mt*2+1],
                                  acc[mt][nt][3] * sc[mt*2+1]);
                *reinterpret_cast<uint32_t*>(C + (long long)m * ldc + n) = u0;
                *reinterpret_cast<uint32_t*>(C + (long long)(m + 8) * ldc + n) = u1;
            }
    }
}

// ---------------------------------------------------------------------------
// Transpose: out[c][r] = fp16(in[r][c])
// ---------------------------------------------------------------------------
__global__ void transpose_h(const float* __restrict__ in, int ldi, long long inZ,
                            __half* __restrict__ oh, int ldo, long long outZ) {
    __shared__ float t[32][33];
    in += blockIdx.z * inZ;
    const long long ob = blockIdx.z * outZ;
    const int r0 = blockIdx.y * 32, c0 = blockIdx.x * 32;
    #pragma unroll
    for (int i = threadIdx.y; i < 32; i += 8)
        t[i][threadIdx.x] = in[(long long)(r0 + i) * ldi + c0 + threadIdx.x];
    __syncthreads();
    #pragma unroll
    for (int i = threadIdx.y; i < 32; i += 8) {
        long long o = ob + (long long)(c0 + i) * ldo + r0 + threadIdx.x;
        oh[o] = __float2half_rn(t[threadIdx.x][i]);
    }
}

// ---------------------------------------------------------------------------
// Row (128) L2-normalize + per-head scale, emit fp16 (keys)
// ---------------------------------------------------------------------------
__global__ void normalize_h(const float* __restrict__ src,
                            __half* __restrict__ hi,
                            const float* __restrict__ attn_scale, int nrows) {
    int row  = blockIdx.x * (blockDim.x >> 5) + (threadIdx.x >> 5);
    int lane = threadIdx.x & 31;
    if (row >= nrows) return;
    float4 v = reinterpret_cast<const float4*>(src + (size_t)row * HDIM)[lane];
    float ss = v.x * v.x + v.y * v.y + v.z * v.z + v.w * v.w;
    #pragma unroll
    for (int o = 16; o; o >>= 1) ss += __shfl_xor_sync(0xFFFFFFFFu, ss, o);
    float sc = rsqrtf(ss + EPSN) * attn_scale[row & (NHEADS - 1)];
    size_t off = (size_t)row * HDIM + lane * 4;
    *reinterpret_cast<uint32_t*>(hi + off)     = pkh(v.x * sc, v.y * sc);
    *reinterpret_cast<uint32_t*>(hi + off + 2) = pkh(v.z * sc, v.w * sc);
}

// ---------------------------------------------------------------------------
// Launch (side stream prep; fork/join via events)
// ---------------------------------------------------------------------------
extern "C" void kernel_launch(void* const* d_in, const int* in_sizes, int n_in,
                              void* d_out, int out_size) {
    const float* x     = (const float*)d_in[0];
    const float* Wq    = (const float*)d_in[1];
    const float* keys  = (const float*)d_in[2];
    const float* vals  = (const float*)d_in[3];
    const float* ascal = (const float*)d_in[4];
    const float* Wo    = (const float*)d_in[5];
    float* out = (float*)d_out;

    __half *wqh, *woh, *qh, *kh, *vth, *yh;
    cudaGetSymbolAddress((void**)&wqh, g_wqt_h);
    cudaGetSymbolAddress((void**)&woh, g_wot_h);
    cudaGetSymbolAddress((void**)&qh, g_qh);
    cudaGetSymbolAddress((void**)&kh, g_kh);
    cudaGetSymbolAddress((void**)&vth, g_vth);
    cudaGetSymbolAddress((void**)&yh, g_yh);

    cudaFuncSetAttribute((const void*)gemm_mma<0,0>,
                         cudaFuncAttributeMaxDynamicSharedMemorySize, SMEM_GEMM);
    cudaFuncSetAttribute((const void*)gemm_mma<1,1>,
                         cudaFuncAttributeMaxDynamicSharedMemorySize, SMEM_GEMM);
    cudaFuncSetAttribute((const void*)attn_fused,
                         cudaFuncAttributeMaxDynamicSharedMemorySize, SMEM_ATTN);

    static cudaStream_t s1 = nullptr;
    static cudaEvent_t evF = nullptr, evW = nullptr, evJ = nullptr;
    if (!s1) {
        cudaStreamCreateWithFlags(&s1, cudaStreamNonBlocking);
        cudaEventCreateWithFlags(&evF, cudaEventDisableTiming);
        cudaEventCreateWithFlags(&evW, cudaEventDisableTiming);
        cudaEventCreateWithFlags(&evJ, cudaEventDisableTiming);
    }

    // fork: side stream — WqT first (gates Q-proj), then hidden prep
    cudaEventRecord(evF, 0);
    cudaStreamWaitEvent(s1, evF, 0);
    transpose_h<<<dim3(32, 32, 1), dim3(32, 8), 0, s1>>>(Wq, DMODEL, 0, wqh, DMODEL, 0);
    cudaEventRecord(evW, s1);
    normalize_h<<<(NHID * NHEADS) / 8, 256, 0, s1>>>(keys, kh, ascal, NHID * NHEADS);
    transpose_h<<<dim3(HDIM / 32, NHID / 32, NHEADS), dim3(32, 8), 0, s1>>>(
        vals, DMODEL, (long long)HDIM, vth, NHID, (long long)HDIM * NHID);
    transpose_h<<<dim3(32, 32, 1), dim3(32, 8), 0, s1>>>(Wo, DMODEL, 0, woh, DMODEL, 0);
    cudaEventRecord(evJ, s1);

    // main: Q-proj with fused fp32->fp16 conversion of x and fused q-normalize
    cudaStreamWaitEvent(0, evW, 0);
    gemm_mma<1,1><<<dim3(S_LEN / 128, DMODEL / 128), 256, SMEM_GEMM>>>(
        x, wqh, qh, DMODEL, DMODEL, DMODEL, DMODEL);

    // join side stream, then attention
    cudaStreamWaitEvent(0, evJ, 0);
    attn_fused<<<dim3(S_LEN / 128, NHEADS), 256, SMEM_ATTN>>>(qh, kh, vth, yh);

    // O-proj (1-term) -> fp32 out
    gemm_mma<0,0><<<dim3(S_LEN / 128, DMODEL / 128), 256, SMEM_GEMM>>>(
        yh, woh, out, DMODEL, DMODEL, DMODEL, DMODEL);
}